// round 3
// baseline (speedup 1.0000x reference)
#include <cuda_runtime.h>
#include <cfloat>

// Problem constants
#define E_DIM   64
#define K_CODE  1024
#define BM      64
#define BN      128

// Output layout (float32, tuple order):
// z_q_st[16,4096,64], diff[1], embed_ind[16,4096], new_embed[1024,64],
// new_cluster_size[1024], new_embed_avg[1024,64]
#define OFF_ZQ   0
#define OFF_DIFF 4194304
#define OFF_IND  4194305
#define OFF_NEMB 4259841
#define OFF_NCS  4325377
#define OFF_NEA  4326401

__device__ float  g_wnorm[K_CODE];
__device__ double g_diff_acc;

// ---------------------------------------------------------------------------
// k_init: wnorm[k] = strict sequential sum of fl(w_i^2)  (XLA-CPU reduce order);
// seed EMA outputs with decay*old; zero diff accumulator.
// ---------------------------------------------------------------------------
__global__ void k_init(const float* __restrict__ embed,
                       const float* __restrict__ cluster,
                       const float* __restrict__ eavg,
                       float* __restrict__ out) {
    int t = blockIdx.x * blockDim.x + threadIdx.x;   // 65536 threads
    out[OFF_NEA + t] = 0.99f * eavg[t];              // region only 4B-aligned
    if (t < K_CODE) {
        out[OFF_NCS + t] = 0.99f * cluster[t];
        const float* w = embed + (size_t)t * E_DIM;
        float s = 0.f;
        #pragma unroll
        for (int i = 0; i < E_DIM; i++)
            s = __fadd_rn(s, __fmul_rn(w[i], w[i]));  // rounded square, seq add
        g_wnorm[t] = s;
    }
    if (t == 0) g_diff_acc = 0.0;
}

// ---------------------------------------------------------------------------
// k_main: 64-token tile vs all 1024 codes. dist replicates reference fp32:
//   dot2   = sequential-k FMA chain of x_k * (2 w_k)      (Eigen gebp order)
//   xnorm  = sequential add of rounded squares
//   dist   = fl( fl(xnorm - dot2) + wnorm )
// argmin: strict <, lowest index on exact ties. Fused epilogue.
// ---------------------------------------------------------------------------
__global__ void __launch_bounds__(128, 3)
k_main(const float* __restrict__ z_e, const float* __restrict__ embed,
       float* __restrict__ out) {
    __shared__ float Xs[E_DIM][BM];   // k-major X tile (raw x), 16KB
    __shared__ float Ws[E_DIM][BN];   // k-major 2*W tile, 32KB
    __shared__ float xn[BM];          // per-token xnorm (reference order)

    const int tid = threadIdx.x;      // 128 threads
    const int tx = tid & 15;          // 16 groups of 8 codes  -> 128 codes
    const int ty = tid >> 4;          // 8  groups of 8 tokens -> 64 tokens
    const int tbase = blockIdx.x * BM;

    // Load X tile transposed: 4096 floats = 1024 float4, 8 per thread
    #pragma unroll
    for (int r = 0; r < 8; r++) {
        int v = tid + r * 128;
        int m = v >> 4;
        int e4 = (v & 15) << 2;
        float4 x = *(const float4*)(z_e + (size_t)(tbase + m) * E_DIM + e4);
        Xs[e4 + 0][m] = x.x; Xs[e4 + 1][m] = x.y;
        Xs[e4 + 2][m] = x.z; Xs[e4 + 3][m] = x.w;
    }
    __syncthreads();

    // xnorm per token, exact reference order: seq add of rounded squares, k asc
    if (tid < BM) {
        float s = 0.f;
        #pragma unroll
        for (int k = 0; k < E_DIM; k++) {
            float v = Xs[k][tid];
            s = __fadd_rn(s, __fmul_rn(v, v));
        }
        xn[tid] = s;
    }
    __syncthreads();

    float xnv[8];
    #pragma unroll
    for (int i = 0; i < 8; i++) xnv[i] = xn[ty * 8 + i];

    float bestv[8]; int besti[8];
    #pragma unroll
    for (int i = 0; i < 8; i++) { bestv[i] = FLT_MAX; besti[i] = 0; }

    for (int c = 0; c < K_CODE / BN; c++) {
        __syncthreads();
        // Load W chunk transposed, PRE-SCALED by 2 (exact): 2048 float4
        #pragma unroll
        for (int r = 0; r < 16; r++) {
            int v = tid + r * 128;
            int n = v >> 4;
            int e4 = (v & 15) << 2;
            float4 w = *(const float4*)(embed + (size_t)(c * BN + n) * E_DIM + e4);
            Ws[e4 + 0][n] = 2.f * w.x; Ws[e4 + 1][n] = 2.f * w.y;
            Ws[e4 + 2][n] = 2.f * w.z; Ws[e4 + 3][n] = 2.f * w.w;
        }
        __syncthreads();

        float acc[8][8];
        #pragma unroll
        for (int i = 0; i < 8; i++)
            #pragma unroll
            for (int j = 0; j < 8; j++) acc[i][j] = 0.f;

        // Sequential-k FMA chain per (i,j), k ascending — matches Eigen gebp.
        #pragma unroll 8
        for (int k = 0; k < E_DIM; k++) {
            float4 a0 = *(const float4*)&Xs[k][ty * 8];
            float4 a1 = *(const float4*)&Xs[k][ty * 8 + 4];
            float4 b0 = *(const float4*)&Ws[k][tx * 8];
            float4 b1 = *(const float4*)&Ws[k][tx * 8 + 4];
            float av[8] = {a0.x, a0.y, a0.z, a0.w, a1.x, a1.y, a1.z, a1.w};
            float bv[8] = {b0.x, b0.y, b0.z, b0.w, b1.x, b1.y, b1.z, b1.w};
            #pragma unroll
            for (int i = 0; i < 8; i++)
                #pragma unroll
                for (int j = 0; j < 8; j++)
                    acc[i][j] = __fmaf_rn(av[i], bv[j], acc[i][j]);
        }

        // dist = fl(fl(xnorm - dot2) + wnorm); ascending idx + strict '<'
        // keeps the lowest index on exact ties (matches jnp.argmin).
        #pragma unroll
        for (int j = 0; j < 8; j++) {
            int idx = c * BN + tx * 8 + j;
            float wn = g_wnorm[idx];
            #pragma unroll
            for (int i = 0; i < 8; i++) {
                float r2 = __fadd_rn(__fsub_rn(xnv[i], acc[i][j]), wn);
                if (r2 < bestv[i]) { bestv[i] = r2; besti[i] = idx; }
            }
        }
    }
    __syncthreads();   // all Xs reads done; safe to alias reduction buffers

    float* sv  = &Xs[0][0];                // [64][16]
    int*   si  = (int*)(&Xs[0][0] + 1024); // [64][16]
    int*   fin = si + 64 * 16;             // [64]

    #pragma unroll
    for (int i = 0; i < 8; i++) {
        int m = ty * 8 + i;
        sv[m * 16 + tx] = bestv[i];
        si[m * 16 + tx] = besti[i];
    }
    __syncthreads();

    if (tid < 64) {
        float bv = sv[tid * 16]; int bi = si[tid * 16];
        #pragma unroll
        for (int t = 1; t < 16; t++) {
            float v = sv[tid * 16 + t]; int ii = si[tid * 16 + t];
            if (v < bv || (v == bv && ii < bi)) { bv = v; bi = ii; }
        }
        fin[tid] = bi;
        out[OFF_IND + tbase + tid] = (float)bi;
    }
    __syncthreads();

    // Epilogue: 2 threads per token, 32 dims each.
    {
        int m = tid >> 1;
        int half = (tid & 1) * 32;
        int idx = fin[m];
        const float* zr = z_e + (size_t)(tbase + m) * E_DIM + half;
        const float* qr = embed + (size_t)idx * E_DIM + half;
        float* orow = out + OFF_ZQ + (size_t)(tbase + m) * E_DIM + half;
        float* srow = out + OFF_NEA + (size_t)idx * E_DIM + half;
        float ldiff = 0.f;
        #pragma unroll
        for (int u = 0; u < 8; u++) {
            float4 z = *(const float4*)(zr + 4 * u);
            float4 q = *(const float4*)(qr + 4 * u);
            // d = fl(q-z); out = fl(z+d)  — matches straight-through reference
            float4 d = make_float4(__fsub_rn(q.x, z.x), __fsub_rn(q.y, z.y),
                                   __fsub_rn(q.z, z.z), __fsub_rn(q.w, z.w));
            ldiff += d.x * d.x + d.y * d.y + d.z * d.z + d.w * d.w;
            float4 o = make_float4(__fadd_rn(z.x, d.x), __fadd_rn(z.y, d.y),
                                   __fadd_rn(z.z, d.z), __fadd_rn(z.w, d.w));
            *(float4*)(orow + 4 * u) = o;
            atomicAdd(srow + 4 * u + 0, 0.01f * z.x);
            atomicAdd(srow + 4 * u + 1, 0.01f * z.y);
            atomicAdd(srow + 4 * u + 2, 0.01f * z.z);
            atomicAdd(srow + 4 * u + 3, 0.01f * z.w);
        }
        if ((tid & 1) == 0) atomicAdd(out + OFF_NCS + idx, 0.01f);

        // block-reduce diff partial, one double atomic per block
        #pragma unroll
        for (int o = 16; o > 0; o >>= 1)
            ldiff += __shfl_down_sync(0xffffffffu, ldiff, o);
        float* dsum = &Ws[0][0];   // alias (Ws no longer needed)
        if ((tid & 31) == 0) dsum[tid >> 5] = ldiff;
        __syncthreads();
        if (tid == 0)
            atomicAdd(&g_diff_acc,
                      (double)dsum[0] + (double)dsum[1] +
                      (double)dsum[2] + (double)dsum[3]);
    }
}

// ---------------------------------------------------------------------------
// k_final: n = sum(new_cluster_size); cs normalize; new_embed; diff
// All accesses to odd-offset regions are SCALAR (4B-aligned only).
// ---------------------------------------------------------------------------
__global__ void k_final(float* __restrict__ out) {
    __shared__ float red[1024];
    int k = threadIdx.x;
    float c = out[OFF_NCS + k];
    red[k] = c;
    __syncthreads();
    for (int o = 512; o > 0; o >>= 1) {
        if (k < o) red[k] += red[k + o];
        __syncthreads();
    }
    float n = red[0];
    float cs = (c + 1e-5f) / (n + 1024.0f * 1e-5f) * n;
    const float* src = out + OFF_NEA  + (size_t)k * E_DIM;
    float*       dst = out + OFF_NEMB + (size_t)k * E_DIM;
    #pragma unroll
    for (int u = 0; u < E_DIM; u++) {
        dst[u] = src[u] / cs;
    }
    if (k == 0) out[OFF_DIFF] = (float)(g_diff_acc * (1.0 / 4194304.0));
}

// ---------------------------------------------------------------------------
extern "C" void kernel_launch(void* const* d_in, const int* in_sizes, int n_in,
                              void* d_out, int out_size) {
    const float* z_e     = (const float*)d_in[0];
    const float* embed   = (const float*)d_in[1];
    const float* cluster = (const float*)d_in[2];
    const float* eavg    = (const float*)d_in[3];
    float* out = (float*)d_out;

    int T = in_sizes[0] / E_DIM;     // 65536 tokens

    k_init<<<256, 256>>>(embed, cluster, eavg, out);
    k_main<<<T / BM, 128>>>(z_e, embed, out);
    k_final<<<1, 1024>>>(out);
}

// round 4
// speedup vs baseline: 1.1036x; 1.1036x over previous
#include <cuda_runtime.h>
#include <cfloat>
#include <cstdint>

// Problem constants
#define E_DIM   64
#define K_CODE  1024
#define BM      64
#define BN      128

// Output layout (float32, tuple order):
// z_q_st[16,4096,64], diff[1], embed_ind[16,4096], new_embed[1024,64],
// new_cluster_size[1024], new_embed_avg[1024,64]
#define OFF_ZQ   0
#define OFF_DIFF 4194304
#define OFF_IND  4194305
#define OFF_NEMB 4259841
#define OFF_NCS  4325377
#define OFF_NEA  4326401

__device__ float  g_wnorm[K_CODE];
__device__ double g_diff_acc;

// ---- packed fp32x2 helpers (sm_103a; bit-exact IEEE fp32 per lane) --------
__device__ __forceinline__ uint64_t pack2(float lo, float hi) {
    uint64_t r;
    asm("mov.b64 %0, {%1, %2};" : "=l"(r) : "f"(lo), "f"(hi));
    return r;
}
__device__ __forceinline__ void unpack2(uint64_t v, float& lo, float& hi) {
    asm("mov.b64 {%0, %1}, %2;" : "=f"(lo), "=f"(hi) : "l"(v));
}
__device__ __forceinline__ void ffma2(uint64_t& d, uint64_t a, uint64_t b) {
    // d.lo = fl(a.lo*b.lo + d.lo); d.hi = fl(a.hi*b.hi + d.hi)
    asm("fma.rn.f32x2 %0, %1, %2, %0;" : "+l"(d) : "l"(a), "l"(b));
}

// ---------------------------------------------------------------------------
// k_init: wnorm[k] = strict sequential sum of fl(w_i^2); seed EMA outputs.
// ---------------------------------------------------------------------------
__global__ void k_init(const float* __restrict__ embed,
                       const float* __restrict__ cluster,
                       const float* __restrict__ eavg,
                       float* __restrict__ out) {
    int t = blockIdx.x * blockDim.x + threadIdx.x;   // 65536 threads
    out[OFF_NEA + t] = 0.99f * eavg[t];              // region only 4B-aligned
    if (t < K_CODE) {
        out[OFF_NCS + t] = 0.99f * cluster[t];
        const float* w = embed + (size_t)t * E_DIM;
        float s = 0.f;
        #pragma unroll
        for (int i = 0; i < E_DIM; i++)
            s = __fadd_rn(s, __fmul_rn(w[i], w[i]));  // rounded square, seq add
        g_wnorm[t] = s;
    }
    if (t == 0) g_diff_acc = 0.0;
}

// ---------------------------------------------------------------------------
// k_main: 64-token tile vs all 1024 codes. dist replicates reference fp32:
//   dot2  = sequential-k FMA chain of x_k * (2 w_k)   (now via fma.rn.f32x2,
//           lanes = two tokens, bit-identical to scalar __fmaf_rn chain)
//   dist  = fl( fl(xnorm - dot2) + wnorm )
// argmin: strict <, lowest index on exact ties. Fused epilogue.
// ---------------------------------------------------------------------------
__global__ void __launch_bounds__(128, 3)
k_main(const float* __restrict__ z_e, const float* __restrict__ embed,
       float* __restrict__ out) {
    __shared__ float Xs[E_DIM][BM];   // k-major X tile (raw x), 16KB
    __shared__ float Ws[E_DIM][BN];   // k-major 2*W tile, 32KB
    __shared__ float xn[BM];          // per-token xnorm (reference order)

    const int tid = threadIdx.x;      // 128 threads
    const int tx = tid & 15;          // 16 groups of 8 codes  -> 128 codes
    const int ty = tid >> 4;          // 8  groups of 8 tokens -> 64 tokens
    const int tbase = blockIdx.x * BM;

    // Load X tile transposed: 4096 floats = 1024 float4, 8 per thread
    #pragma unroll
    for (int r = 0; r < 8; r++) {
        int v = tid + r * 128;
        int m = v >> 4;
        int e4 = (v & 15) << 2;
        float4 x = *(const float4*)(z_e + (size_t)(tbase + m) * E_DIM + e4);
        Xs[e4 + 0][m] = x.x; Xs[e4 + 1][m] = x.y;
        Xs[e4 + 2][m] = x.z; Xs[e4 + 3][m] = x.w;
    }
    __syncthreads();

    // xnorm per token, exact reference order: seq add of rounded squares
    if (tid < BM) {
        float s = 0.f;
        #pragma unroll
        for (int k = 0; k < E_DIM; k++) {
            float v = Xs[k][tid];
            s = __fadd_rn(s, __fmul_rn(v, v));
        }
        xn[tid] = s;
    }
    __syncthreads();

    float xnv[8];
    #pragma unroll
    for (int i = 0; i < 8; i++) xnv[i] = xn[ty * 8 + i];

    float bestv[8]; int besti[8];
    #pragma unroll
    for (int i = 0; i < 8; i++) { bestv[i] = FLT_MAX; besti[i] = 0; }

    for (int c = 0; c < K_CODE / BN; c++) {
        __syncthreads();
        // Load W chunk transposed, PRE-SCALED by 2 (exact): 2048 float4
        #pragma unroll
        for (int r = 0; r < 16; r++) {
            int v = tid + r * 128;
            int n = v >> 4;
            int e4 = (v & 15) << 2;
            float4 w = *(const float4*)(embed + (size_t)(c * BN + n) * E_DIM + e4);
            Ws[e4 + 0][n] = 2.f * w.x; Ws[e4 + 1][n] = 2.f * w.y;
            Ws[e4 + 2][n] = 2.f * w.z; Ws[e4 + 3][n] = 2.f * w.w;
        }
        __syncthreads();

        // acc2[p][j]: token pair (2p,2p+1) x code j, packed fp32x2
        uint64_t acc2[4][8];
        #pragma unroll
        for (int p = 0; p < 4; p++)
            #pragma unroll
            for (int j = 0; j < 8; j++) acc2[p][j] = 0ull;

        // Sequential-k FMA chain per (token, code), k ascending.
        #pragma unroll 4
        for (int k = 0; k < E_DIM; k++) {
            float4 a0 = *(const float4*)&Xs[k][ty * 8];
            float4 a1 = *(const float4*)&Xs[k][ty * 8 + 4];
            float4 b0 = *(const float4*)&Ws[k][tx * 8];
            float4 b1 = *(const float4*)&Ws[k][tx * 8 + 4];
            uint64_t A[4];
            A[0] = pack2(a0.x, a0.y); A[1] = pack2(a0.z, a0.w);
            A[2] = pack2(a1.x, a1.y); A[3] = pack2(a1.z, a1.w);
            float bvs[8] = {b0.x, b0.y, b0.z, b0.w, b1.x, b1.y, b1.z, b1.w};
            #pragma unroll
            for (int j = 0; j < 8; j++) {
                uint64_t B = pack2(bvs[j], bvs[j]);
                #pragma unroll
                for (int p = 0; p < 4; p++)
                    ffma2(acc2[p][j], A[p], B);
            }
        }

        // dist = fl(fl(xnorm - dot2) + wnorm); ascending idx + strict '<'
        // keeps the lowest index on exact ties (matches jnp.argmin).
        #pragma unroll
        for (int j = 0; j < 8; j++) {
            int idx = c * BN + tx * 8 + j;
            float wn = g_wnorm[idx];
            #pragma unroll
            for (int p = 0; p < 4; p++) {
                float dlo, dhi;
                unpack2(acc2[p][j], dlo, dhi);
                float r2lo = __fadd_rn(__fsub_rn(xnv[2 * p], dlo), wn);
                float r2hi = __fadd_rn(__fsub_rn(xnv[2 * p + 1], dhi), wn);
                if (r2lo < bestv[2 * p])     { bestv[2 * p]     = r2lo; besti[2 * p]     = idx; }
                if (r2hi < bestv[2 * p + 1]) { bestv[2 * p + 1] = r2hi; besti[2 * p + 1] = idx; }
            }
        }
    }
    __syncthreads();   // all Xs reads done; safe to alias reduction buffers

    float* sv  = &Xs[0][0];                // [64][16]
    int*   si  = (int*)(&Xs[0][0] + 1024); // [64][16]
    int*   fin = si + 64 * 16;             // [64]

    #pragma unroll
    for (int i = 0; i < 8; i++) {
        int m = ty * 8 + i;
        sv[m * 16 + tx] = bestv[i];
        si[m * 16 + tx] = besti[i];
    }
    __syncthreads();

    if (tid < 64) {
        float bv = sv[tid * 16]; int bi = si[tid * 16];
        #pragma unroll
        for (int t = 1; t < 16; t++) {
            float v = sv[tid * 16 + t]; int ii = si[tid * 16 + t];
            if (v < bv || (v == bv && ii < bi)) { bv = v; bi = ii; }
        }
        fin[tid] = bi;
        out[OFF_IND + tbase + tid] = (float)bi;
    }
    __syncthreads();

    // Epilogue: 2 threads per token, 32 dims each.
    {
        int m = tid >> 1;
        int half = (tid & 1) * 32;
        int idx = fin[m];
        const float* zr = z_e + (size_t)(tbase + m) * E_DIM + half;
        const float* qr = embed + (size_t)idx * E_DIM + half;
        float* orow = out + OFF_ZQ + (size_t)(tbase + m) * E_DIM + half;
        float* srow = out + OFF_NEA + (size_t)idx * E_DIM + half;
        float ldiff = 0.f;
        #pragma unroll
        for (int u = 0; u < 8; u++) {
            float4 z = *(const float4*)(zr + 4 * u);
            float4 q = *(const float4*)(qr + 4 * u);
            float4 d = make_float4(__fsub_rn(q.x, z.x), __fsub_rn(q.y, z.y),
                                   __fsub_rn(q.z, z.z), __fsub_rn(q.w, z.w));
            ldiff += d.x * d.x + d.y * d.y + d.z * d.z + d.w * d.w;
            float4 o = make_float4(__fadd_rn(z.x, d.x), __fadd_rn(z.y, d.y),
                                   __fadd_rn(z.z, d.z), __fadd_rn(z.w, d.w));
            *(float4*)(orow + 4 * u) = o;
            atomicAdd(srow + 4 * u + 0, 0.01f * z.x);
            atomicAdd(srow + 4 * u + 1, 0.01f * z.y);
            atomicAdd(srow + 4 * u + 2, 0.01f * z.z);
            atomicAdd(srow + 4 * u + 3, 0.01f * z.w);
        }
        if ((tid & 1) == 0) atomicAdd(out + OFF_NCS + idx, 0.01f);

        // block-reduce diff partial, one double atomic per block
        #pragma unroll
        for (int o = 16; o > 0; o >>= 1)
            ldiff += __shfl_down_sync(0xffffffffu, ldiff, o);
        float* dsum = &Ws[0][0];   // alias (Ws no longer needed)
        if ((tid & 31) == 0) dsum[tid >> 5] = ldiff;
        __syncthreads();
        if (tid == 0)
            atomicAdd(&g_diff_acc,
                      (double)dsum[0] + (double)dsum[1] +
                      (double)dsum[2] + (double)dsum[3]);
    }
}

// ---------------------------------------------------------------------------
// k_final: n = sum(new_cluster_size); cs normalize; new_embed; diff
// All accesses to odd-offset regions are SCALAR (4B-aligned only).
// ---------------------------------------------------------------------------
__global__ void k_final(float* __restrict__ out) {
    __shared__ float red[1024];
    int k = threadIdx.x;
    float c = out[OFF_NCS + k];
    red[k] = c;
    __syncthreads();
    for (int o = 512; o > 0; o >>= 1) {
        if (k < o) red[k] += red[k + o];
        __syncthreads();
    }
    float n = red[0];
    float cs = (c + 1e-5f) / (n + 1024.0f * 1e-5f) * n;
    const float* src = out + OFF_NEA  + (size_t)k * E_DIM;
    float*       dst = out + OFF_NEMB + (size_t)k * E_DIM;
    #pragma unroll
    for (int u = 0; u < E_DIM; u++) {
        dst[u] = src[u] / cs;
    }
    if (k == 0) out[OFF_DIFF] = (float)(g_diff_acc * (1.0 / 4194304.0));
}

// ---------------------------------------------------------------------------
extern "C" void kernel_launch(void* const* d_in, const int* in_sizes, int n_in,
                              void* d_out, int out_size) {
    const float* z_e     = (const float*)d_in[0];
    const float* embed   = (const float*)d_in[1];
    const float* cluster = (const float*)d_in[2];
    const float* eavg    = (const float*)d_in[3];
    float* out = (float*)d_out;

    int T = in_sizes[0] / E_DIM;     // 65536 tokens

    k_init<<<512, 128>>>(embed, cluster, eavg, out);
    k_main<<<T / BM, 128>>>(z_e, embed, out);
    k_final<<<1, 1024>>>(out);
}